// round 1
// baseline (speedup 1.0000x reference)
#include <cuda_runtime.h>
#include <cstddef>

#define LSTM_B 512
#define LSTM_S 2048
#define LSTM_H 64
#define GB 4                   // batch elements per CTA
#define NCTA (LSTM_B / GB)     // 128 CTAs
#define NTH 256                // one gate row per thread

// Scratch: intermediate hidden-state sequences (sanctioned __device__ globals).
__device__ float g_bufA[(size_t)LSTM_B * LSTM_S * LSTM_H];
__device__ float g_bufB[(size_t)LSTM_B * LSTM_S * LSTM_H];

__device__ __forceinline__ float sigf(float z) {
    return 1.0f / (1.0f + __expf(-z));
}
__device__ __forceinline__ float tanhfast(float z) {
    // tanh(z) = 1 - 2/(e^{2z}+1); saturates correctly at +/-inf
    return 1.0f - 2.0f / (__expf(2.0f * z) + 1.0f);
}

// One LSTM layer, persistent over the full sequence.
// x   : [B][S][IN]   (IN = 4 for layer 0, 64 for layers 1,2)
// Wih : [4H][IN], Whh : [4H][H], bih/bhh : [4H]
// out : [B][S][H]
template <int IN>
__global__ void __launch_bounds__(NTH, 1)
lstm_layer_kernel(const float* __restrict__ x,
                  const float* __restrict__ Wih,
                  const float* __restrict__ Whh,
                  const float* __restrict__ bih,
                  const float* __restrict__ bhh,
                  float* __restrict__ out)
{
    constexpr int KD = IN + LSTM_H;                    // 68 or 128
    constexpr int ST = KD + (((36 - (KD & 31)) & 31)); // pad so ST % 32 == 4 -> bank-conflict-free
    constexpr int K4 = ST / 4;

    extern __shared__ float sm[];
    float* Wsh  = sm;                   // [256][ST]  combined [Wih|Whh|pad]
    float* bias = Wsh + 256 * ST;       // [256]
    float* xh   = bias + 256;           // [GB][ST]   combined [x_t|h|pad]
    float* gsh  = xh + GB * ST;         // [GB][256]  activated gates
    float* csh  = gsh + GB * 256;       // [GB][64]   cell state

    const int tid = threadIdx.x;
    const int b0  = blockIdx.x * GB;

    // --- load weights / bias, zero state & pads ---
    for (int i = tid; i < 256 * ST; i += NTH) {
        int r = i / ST;
        int k = i - r * ST;
        float w = 0.0f;
        if (k < IN)      w = Wih[r * IN + k];
        else if (k < KD) w = Whh[r * LSTM_H + (k - IN)];
        Wsh[i] = w;
    }
    for (int i = tid; i < 256; i += NTH)     bias[i] = bih[i] + bhh[i];
    for (int i = tid; i < GB * ST; i += NTH) xh[i]   = 0.0f;
    for (int i = tid; i < GB * 64; i += NTH) csh[i]  = 0.0f;
    __syncthreads();

    const float myb = bias[tid];

    // --- input prefetch mapping: thread loads one x element per step ---
    const bool xact = (tid < GB * IN);
    const int  xb   = xact ? (tid / IN) : 0;
    const int  xk   = xact ? (tid - xb * IN) : 0;
    const float* xp = x + ((size_t)(b0 + xb)) * LSTM_S * IN + xk;
    float xpre = xact ? xp[0] : 0.0f;

    const int gt = tid >> 6;    // gate type: 0=i 1=f 2=g 3=o
    const int ub = tid >> 6;    // update phase: batch index
    const int uu = tid & 63;    // update phase: hidden unit

    for (int t = 0; t < LSTM_S; ++t) {
        // publish x_t (prefetched last step)
        if (xact) xh[xb * ST + xk] = xpre;
        __syncthreads();   // barrier 1: x_t and h_{t-1} visible

        // prefetch x_{t+1} (latency hidden under the FMA loop)
        if (xact && (t + 1 < LSTM_S)) xpre = xp[(size_t)(t + 1) * IN];

        // --- gates: each thread = one gate row, 4 batch elements ---
        float acc0 = 0.0f, acc1 = 0.0f, acc2 = 0.0f, acc3 = 0.0f;
        const float4* Wr = reinterpret_cast<const float4*>(Wsh + tid * ST);
        const float4* v0 = reinterpret_cast<const float4*>(xh);
        const float4* v1 = reinterpret_cast<const float4*>(xh + ST);
        const float4* v2 = reinterpret_cast<const float4*>(xh + 2 * ST);
        const float4* v3 = reinterpret_cast<const float4*>(xh + 3 * ST);
#pragma unroll
        for (int k = 0; k < K4; ++k) {
            const float4 w = Wr[k];
            float4 a;
            a = v0[k]; acc0 += w.x * a.x + w.y * a.y + w.z * a.z + w.w * a.w;
            a = v1[k]; acc1 += w.x * a.x + w.y * a.y + w.z * a.z + w.w * a.w;
            a = v2[k]; acc2 += w.x * a.x + w.y * a.y + w.z * a.z + w.w * a.w;
            a = v3[k]; acc3 += w.x * a.x + w.y * a.y + w.z * a.z + w.w * a.w;
        }
        float z0 = acc0 + myb, z1 = acc1 + myb, z2 = acc2 + myb, z3 = acc3 + myb;
        float a0, a1, a2, a3;
        if (gt == 2) {
            a0 = tanhfast(z0); a1 = tanhfast(z1); a2 = tanhfast(z2); a3 = tanhfast(z3);
        } else {
            a0 = sigf(z0); a1 = sigf(z1); a2 = sigf(z2); a3 = sigf(z3);
        }
        gsh[tid]       = a0;
        gsh[256 + tid] = a1;
        gsh[512 + tid] = a2;
        gsh[768 + tid] = a3;
        __syncthreads();   // barrier 2: gates visible

        // --- state update: thread -> (batch ub, unit uu) ---
        {
            const float gi = gsh[ub * 256 + uu];
            const float gf = gsh[ub * 256 + 64 + uu];
            const float gg = gsh[ub * 256 + 128 + uu];
            const float go = gsh[ub * 256 + 192 + uu];
            float c = gf * csh[ub * 64 + uu] + gi * gg;
            csh[ub * 64 + uu] = c;
            float h = go * tanhfast(c);
            xh[ub * ST + IN + uu] = h;   // h for next step (read after next barrier 1)
            out[((size_t)(b0 + ub)) * LSTM_S * LSTM_H + (size_t)t * LSTM_H + uu] = h;
        }
        // no trailing barrier needed: next iteration's barrier 1 orders the h writes
    }
}

// out[b] = h_last[b] @ fc_w^T + fc_b   (fc_w: [2][64])
__global__ void fc_kernel(const float* __restrict__ hbuf,
                          const float* __restrict__ fw,
                          const float* __restrict__ fb,
                          float* __restrict__ outp)
{
    int b = blockIdx.x * blockDim.x + threadIdx.x;
    if (b >= LSTM_B) return;
    const float* h = hbuf + ((size_t)b * LSTM_S + (LSTM_S - 1)) * LSTM_H;
    float a0 = fb[0], a1 = fb[1];
#pragma unroll
    for (int k = 0; k < LSTM_H; ++k) {
        float hv = h[k];
        a0 += hv * fw[k];
        a1 += hv * fw[LSTM_H + k];
    }
    outp[b * 2 + 0] = a0;
    outp[b * 2 + 1] = a1;
}

extern "C" void kernel_launch(void* const* d_in, const int* in_sizes, int n_in,
                              void* d_out, int out_size)
{
    const float* x    = (const float*)d_in[0];
    const float* Wih0 = (const float*)d_in[1];
    const float* Whh0 = (const float*)d_in[2];
    const float* bih0 = (const float*)d_in[3];
    const float* bhh0 = (const float*)d_in[4];
    const float* Wih1 = (const float*)d_in[5];
    const float* Whh1 = (const float*)d_in[6];
    const float* bih1 = (const float*)d_in[7];
    const float* bhh1 = (const float*)d_in[8];
    const float* Wih2 = (const float*)d_in[9];
    const float* Whh2 = (const float*)d_in[10];
    const float* bih2 = (const float*)d_in[11];
    const float* bhh2 = (const float*)d_in[12];
    const float* fc_w = (const float*)d_in[13];
    const float* fc_b = (const float*)d_in[14];
    float* out = (float*)d_out;

    float *bufA = nullptr, *bufB = nullptr;
    cudaGetSymbolAddress((void**)&bufA, g_bufA);
    cudaGetSymbolAddress((void**)&bufB, g_bufB);

    constexpr int ST0 = 68, ST1 = 132;
    size_t smem0 = (size_t)(256 * ST0 + 256 + GB * ST0 + GB * 256 + GB * 64) * sizeof(float);
    size_t smem1 = (size_t)(256 * ST1 + 256 + GB * ST1 + GB * 256 + GB * 64) * sizeof(float);

    cudaFuncSetAttribute(lstm_layer_kernel<4>,
                         cudaFuncAttributeMaxDynamicSharedMemorySize, (int)smem0);
    cudaFuncSetAttribute(lstm_layer_kernel<64>,
                         cudaFuncAttributeMaxDynamicSharedMemorySize, (int)smem1);

    lstm_layer_kernel<4><<<NCTA, NTH, smem0>>>(x,    Wih0, Whh0, bih0, bhh0, bufA);
    lstm_layer_kernel<64><<<NCTA, NTH, smem1>>>(bufA, Wih1, Whh1, bih1, bhh1, bufB);
    lstm_layer_kernel<64><<<NCTA, NTH, smem1>>>(bufB, Wih2, Whh2, bih2, bhh2, bufA);
    fc_kernel<<<(LSTM_B + 255) / 256, 256>>>(bufA, fc_w, fc_b, out);
}

// round 3
// speedup vs baseline: 1.7441x; 1.7441x over previous
#include <cuda_runtime.h>
#include <cstddef>

typedef unsigned long long ull;

#define LSTM_B 512
#define LSTM_S 2048
#define LSTM_H 64
#define GB 4                   // batch elements per CTA
#define NCTA (LSTM_B / GB)     // 128 CTAs
#define NTH 256                // one gate row per thread

// Scratch: intermediate hidden-state sequences (sanctioned __device__ globals).
__device__ float g_bufA[(size_t)LSTM_B * LSTM_S * LSTM_H];
__device__ float g_bufB[(size_t)LSTM_B * LSTM_S * LSTM_H];

struct alignas(16) UPair { ull lo, hi; };   // 4 floats = 2 f32x2 pairs

__device__ __forceinline__ float ex2a(float x) {
    float y; asm("ex2.approx.ftz.f32 %0, %1;" : "=f"(y) : "f"(x)); return y;
}
__device__ __forceinline__ float rcpa(float x) {
    float y; asm("rcp.approx.ftz.f32 %0, %1;" : "=f"(y) : "f"(x)); return y;
}
// sigmoid(z) = 1/(1+2^(-z*log2e))
__device__ __forceinline__ float sigf(float z) {
    return rcpa(1.0f + ex2a(-1.4426950408889634f * z));
}
// tanh(z) = 1 - 2/(2^(2z*log2e)+1)
__device__ __forceinline__ float tanha(float z) {
    return 1.0f - 2.0f * rcpa(1.0f + ex2a(2.8853900817779268f * z));
}
__device__ __forceinline__ ull ffma2(ull a, ull b, ull c) {
    ull d;
    asm("fma.rn.f32x2 %0, %1, %2, %3;" : "=l"(d) : "l"(a), "l"(b), "l"(c));
    return d;
}
__device__ __forceinline__ float hadd2(ull v) {
    float lo, hi;
    asm("mov.b64 {%0, %1}, %2;" : "=f"(lo), "=f"(hi) : "l"(v));
    return lo + hi;
}

// One LSTM layer, persistent over the full sequence. Thread = one gate row,
// weights held in registers as packed f32x2 k-pairs. Cell state in registers.
// x: [B][S][IN], Wih: [4H][IN], Whh: [4H][H], out: [B][S][H]
template <int IN>
__global__ void __launch_bounds__(NTH, 1)
lstm_layer_kernel(const float* __restrict__ x,
                  const float* __restrict__ Wih,
                  const float* __restrict__ Whh,
                  const float* __restrict__ bih,
                  const float* __restrict__ bhh,
                  float* __restrict__ out)
{
    constexpr int KD = IN + LSTM_H;   // 68 or 128 (both: KD*4 bytes % 16 == 0)
    constexpr int N4 = KD / 4;        // float4 groups: 17 or 32
    constexpr int NP = KD / 2;        // f32x2 pairs: 34 or 64

    __shared__ __align__(16) float xh[GB * KD];   // per-batch [x_t | h] vectors
    __shared__ __align__(16) float gsh[GB * 256]; // activated gates

    const int tid = threadIdx.x;
    const int b0  = blockIdx.x * GB;

    // --- weights into registers: concat [Wih row | Whh row] as b64 k-pairs ---
    ull wv[NP];
    {
        const ull* wi = reinterpret_cast<const ull*>(Wih + tid * IN);
        const ull* wh = reinterpret_cast<const ull*>(Whh + tid * LSTM_H);
#pragma unroll
        for (int p = 0; p < IN / 2; ++p)        wv[p] = wi[p];
#pragma unroll
        for (int p = 0; p < LSTM_H / 2; ++p)    wv[IN / 2 + p] = wh[p];
    }
    const float myb = bih[tid] + bhh[tid];

    // zero xh (x slots overwritten each step; h slots must start at 0)
    for (int i = tid; i < GB * KD; i += NTH) xh[i] = 0.0f;

    // --- input prefetch mapping: one x element per thread per step ---
    const bool xact = (tid < GB * IN);
    const int  xb   = xact ? (tid / IN) : 0;
    const int  xk   = xact ? (tid - xb * IN) : 0;
    const float* xp = x + ((size_t)(b0 + xb)) * LSTM_S * IN + xk;
    float xpre = xact ? xp[0] : 0.0f;

    const int ub = tid >> 6;       // update phase: batch
    const int uu = tid & 63;       // update phase: hidden unit
    const bool is_g = (ub == 2);   // gate rows 128..191 use tanh
    float creg = 0.0f;             // cell state lives in a register
    float* outp = out + ((size_t)(b0 + ub)) * LSTM_S * LSTM_H + uu;

    __syncthreads();               // xh zero-init visible

    for (int t = 0; t < LSTM_S; ++t) {
        if (xact) xh[xb * KD + xk] = xpre;
        __syncthreads();           // barrier 1: x_t and h_{t-1} visible

        if (xact && (t + 1 < LSTM_S)) xpre = xp[(size_t)(t + 1) * IN];

        // --- gates: dot(w_row, [x|h]) for 4 batch elements, f32x2-packed over k ---
        ull acc0 = 0ull, acc1 = 0ull, acc2 = 0ull, acc3 = 0ull;
        const UPair* v0 = reinterpret_cast<const UPair*>(xh);
        const UPair* v1 = reinterpret_cast<const UPair*>(xh + KD);
        const UPair* v2 = reinterpret_cast<const UPair*>(xh + 2 * KD);
        const UPair* v3 = reinterpret_cast<const UPair*>(xh + 3 * KD);
#pragma unroll
        for (int k = 0; k < N4; ++k) {
            const ull wlo = wv[2 * k];
            const ull whi = wv[2 * k + 1];
            UPair a;
            a = v0[k]; acc0 = ffma2(wlo, a.lo, acc0); acc0 = ffma2(whi, a.hi, acc0);
            a = v1[k]; acc1 = ffma2(wlo, a.lo, acc1); acc1 = ffma2(whi, a.hi, acc1);
            a = v2[k]; acc2 = ffma2(wlo, a.lo, acc2); acc2 = ffma2(whi, a.hi, acc2);
            a = v3[k]; acc3 = ffma2(wlo, a.lo, acc3); acc3 = ffma2(whi, a.hi, acc3);
        }
        float z0 = hadd2(acc0) + myb;
        float z1 = hadd2(acc1) + myb;
        float z2 = hadd2(acc2) + myb;
        float z3 = hadd2(acc3) + myb;
        float a0, a1, a2, a3;
        if (is_g) { a0 = tanha(z0); a1 = tanha(z1); a2 = tanha(z2); a3 = tanha(z3); }
        else      { a0 = sigf(z0);  a1 = sigf(z1);  a2 = sigf(z2);  a3 = sigf(z3); }
        gsh[tid]       = a0;
        gsh[256 + tid] = a1;
        gsh[512 + tid] = a2;
        gsh[768 + tid] = a3;
        __syncthreads();           // barrier 2: gates visible

        // --- state update: thread -> (batch ub, unit uu), c in register ---
        {
            const float* gb = gsh + ub * 256;
            const float gi = gb[uu];
            const float gf = gb[64 + uu];
            const float gg = gb[128 + uu];
            const float go = gb[192 + uu];
            creg = gf * creg + gi * gg;
            const float h = go * tanha(creg);
            xh[ub * KD + IN + uu] = h;          // h_t for next step
            outp[(size_t)t * LSTM_H] = h;
        }
        // next iteration's barrier 1 orders the h/gsh writes against reads
    }
}

// out[b] = h_last[b] @ fc_w^T + fc_b   (fc_w: [2][64])
__global__ void fc_kernel(const float* __restrict__ hbuf,
                          const float* __restrict__ fw,
                          const float* __restrict__ fb,
                          float* __restrict__ outp)
{
    int b = blockIdx.x * blockDim.x + threadIdx.x;
    if (b >= LSTM_B) return;
    const float* h = hbuf + ((size_t)b * LSTM_S + (LSTM_S - 1)) * LSTM_H;
    float a0 = fb[0], a1 = fb[1];
#pragma unroll
    for (int k = 0; k < LSTM_H; ++k) {
        float hv = h[k];
        a0 += hv * fw[k];
        a1 += hv * fw[LSTM_H + k];
    }
    outp[b * 2 + 0] = a0;
    outp[b * 2 + 1] = a1;
}

extern "C" void kernel_launch(void* const* d_in, const int* in_sizes, int n_in,
                              void* d_out, int out_size)
{
    const float* x    = (const float*)d_in[0];
    const float* Wih0 = (const float*)d_in[1];
    const float* Whh0 = (const float*)d_in[2];
    const float* bih0 = (const float*)d_in[3];
    const float* bhh0 = (const float*)d_in[4];
    const float* Wih1 = (const float*)d_in[5];
    const float* Whh1 = (const float*)d_in[6];
    const float* bih1 = (const float*)d_in[7];
    const float* bhh1 = (const float*)d_in[8];
    const float* Wih2 = (const float*)d_in[9];
    const float* Whh2 = (const float*)d_in[10];
    const float* bih2 = (const float*)d_in[11];
    const float* bhh2 = (const float*)d_in[12];
    const float* fc_w = (const float*)d_in[13];
    const float* fc_b = (const float*)d_in[14];
    float* out = (float*)d_out;

    float *bufA = nullptr, *bufB = nullptr;
    cudaGetSymbolAddress((void**)&bufA, g_bufA);
    cudaGetSymbolAddress((void**)&bufB, g_bufB);

    lstm_layer_kernel<4><<<NCTA, NTH>>>(x,    Wih0, Whh0, bih0, bhh0, bufA);
    lstm_layer_kernel<64><<<NCTA, NTH>>>(bufA, Wih1, Whh1, bih1, bhh1, bufB);
    lstm_layer_kernel<64><<<NCTA, NTH>>>(bufB, Wih2, Whh2, bih2, bhh2, bufA);
    fc_kernel<<<(LSTM_B + 255) / 256, 256>>>(bufA, fc_w, fc_b, out);
}

// round 4
// speedup vs baseline: 1.7694x; 1.0145x over previous
#include <cuda_runtime.h>
#include <cstddef>

typedef unsigned long long ull;

#define B_   512
#define S_   2048
#define H_   64
#define GB   2                  // batch per recurrent CTA
#define NCTA (B_ / GB)          // 256 recurrent CTAs (2 per SM)
#define NTH  256
#define PST  128                // proj s-tile

// Scratch (sanctioned __device__ globals)
__device__ float g_h0[(size_t)B_ * S_ * H_];        // 256 MB
__device__ float g_h1[(size_t)B_ * S_ * H_];        // 256 MB
__device__ float g_xp[(size_t)B_ * S_ * 4 * H_];    // 1 GB
__device__ float g_hlast[B_ * H_];

struct alignas(16) UPair { ull lo, hi; };

__device__ __forceinline__ float ex2a(float x) {
    float y; asm("ex2.approx.ftz.f32 %0, %1;" : "=f"(y) : "f"(x)); return y;
}
__device__ __forceinline__ float rcpa(float x) {
    float y; asm("rcp.approx.ftz.f32 %0, %1;" : "=f"(y) : "f"(x)); return y;
}
__device__ __forceinline__ float sigf(float z) {
    return rcpa(1.0f + ex2a(-1.4426950408889634f * z));
}
__device__ __forceinline__ float tanha(float z) {
    return 1.0f - 2.0f * rcpa(1.0f + ex2a(2.8853900817779268f * z));
}
__device__ __forceinline__ ull ffma2(ull a, ull b, ull c) {
    ull d;
    asm("fma.rn.f32x2 %0, %1, %2, %3;" : "=l"(d) : "l"(a), "l"(b), "l"(c));
    return d;
}
__device__ __forceinline__ float hadd2(ull v) {
    float lo, hi;
    asm("mov.b64 {%0, %1}, %2;" : "=f"(lo), "=f"(hi) : "l"(v));
    return lo + hi;
}

// ---------------------------------------------------------------------------
// Bulk input projection: out[b][s][r] = dot(in[b][s][:64], W[r][:64]) + bias[r]
// Grid: B_ * (S_/PST) CTAs; thread = output row r, weights register-resident.
// ---------------------------------------------------------------------------
__global__ void __launch_bounds__(NTH, 2)
proj_kernel(const float* __restrict__ in,    // [B][S][64]
            const float* __restrict__ W,     // [256][64]
            const float* __restrict__ bih,
            const float* __restrict__ bhh,
            float* __restrict__ out)         // [B][S][256]
{
    __shared__ __align__(16) float xin[PST * H_];   // 32 KB
    const int tid   = threadIdx.x;
    const int stile = blockIdx.x & (S_ / PST - 1);
    const int b     = blockIdx.x / (S_ / PST);
    const size_t base = (size_t)b * S_ + (size_t)stile * PST;   // (b,s) row index

    ull wv[32];
    {
        const ull* wp = reinterpret_cast<const ull*>(W + tid * H_);
#pragma unroll
        for (int p = 0; p < 32; ++p) wv[p] = wp[p];
    }
    const float myb = bih[tid] + bhh[tid];

    // cooperative coalesced load of the s-tile
    {
        const float4* gsrc = reinterpret_cast<const float4*>(in + base * H_);
        float4* sdst = reinterpret_cast<float4*>(xin);
        for (int i = tid; i < PST * H_ / 4; i += NTH) sdst[i] = gsrc[i];
    }
    __syncthreads();

    for (int sq = 0; sq < PST; sq += 4) {
        ull a0 = 0, a1 = 0, a2 = 0, a3 = 0;
        const UPair* v0 = reinterpret_cast<const UPair*>(xin + (sq + 0) * H_);
        const UPair* v1 = reinterpret_cast<const UPair*>(xin + (sq + 1) * H_);
        const UPair* v2 = reinterpret_cast<const UPair*>(xin + (sq + 2) * H_);
        const UPair* v3 = reinterpret_cast<const UPair*>(xin + (sq + 3) * H_);
#pragma unroll
        for (int k = 0; k < 16; ++k) {
            const ull wlo = wv[2 * k], whi = wv[2 * k + 1];
            UPair a;
            a = v0[k]; a0 = ffma2(wlo, a.lo, a0); a0 = ffma2(whi, a.hi, a0);
            a = v1[k]; a1 = ffma2(wlo, a.lo, a1); a1 = ffma2(whi, a.hi, a1);
            a = v2[k]; a2 = ffma2(wlo, a.lo, a2); a2 = ffma2(whi, a.hi, a2);
            a = v3[k]; a3 = ffma2(wlo, a.lo, a3); a3 = ffma2(whi, a.hi, a3);
        }
        out[(base + sq + 0) * 256 + tid] = hadd2(a0) + myb;
        out[(base + sq + 1) * 256 + tid] = hadd2(a1) + myb;
        out[(base + sq + 2) * 256 + tid] = hadd2(a2) + myb;
        out[(base + sq + 3) * 256 + tid] = hadd2(a3) + myb;
    }
}

// ---------------------------------------------------------------------------
// Recurrent kernel. IN=4: layer 0 (x inline, bias in-kernel).
// IN=0: gates initialized from precomputed xp[b][t][256] (bias folded there).
// GB=2 batches/CTA, 256 CTAs, 2 CTAs/SM. Thread = gate row; Whh row in regs.
// ---------------------------------------------------------------------------
template <int IN, bool LAST_ONLY>
__global__ void __launch_bounds__(NTH, 2)
recur_kernel(const float* __restrict__ xin,   // IN=4: x[B][S][4]; IN=0: xp[B][S][256]
             const float* __restrict__ Wih,   // IN=4 only
             const float* __restrict__ Whh,
             const float* __restrict__ bih,   // IN=4 only
             const float* __restrict__ bhh,   // IN=4 only
             float* __restrict__ out)         // full [B][S][64], or [B][64] last-only
{
    constexpr int KD = IN + H_;   // 68 or 64
    constexpr int N4 = KD / 4;

    __shared__ __align__(16) float xh[GB * KD];    // per-batch [x_t | h]
    __shared__ __align__(16) float gsh[GB * 256];  // activated gates

    const int tid = threadIdx.x;
    const int b0  = blockIdx.x * GB;

    // weights into registers: [Wih row | Whh row] as b64 k-pairs
    ull wv[KD / 2];
    if constexpr (IN > 0) {
        const ull* wi = reinterpret_cast<const ull*>(Wih + tid * IN);
#pragma unroll
        for (int p = 0; p < IN / 2; ++p) wv[p] = wi[p];
    }
    {
        const ull* wh = reinterpret_cast<const ull*>(Whh + tid * H_);
#pragma unroll
        for (int p = 0; p < H_ / 2; ++p) wv[IN / 2 + p] = wh[p];
    }

    float myb = 0.0f;
    if constexpr (IN > 0) myb = bih[tid] + bhh[tid];

    for (int i = tid; i < GB * KD; i += NTH) xh[i] = 0.0f;

    // input prefetch state
    bool xact = false; int xb = 0, xk = 0;
    const float* xp0 = nullptr; const float* xp1 = nullptr;
    float pre0 = 0.0f, pre1 = 0.0f;
    if constexpr (IN > 0) {
        xact = (tid < GB * IN);
        xb   = xact ? (tid / IN) : 0;
        xk   = xact ? (tid - xb * IN) : 0;
        xp0  = xin + ((size_t)(b0 + xb)) * S_ * IN + xk;
        pre0 = xact ? xp0[0] : 0.0f;
    } else {
        xp0  = xin + ((size_t)b0 * S_) * 256 + tid;
        xp1  = xin + ((size_t)(b0 + 1) * S_) * 256 + tid;
        pre0 = xp0[0];
        pre1 = xp1[0];
    }

    const int ub = tid >> 6;          // update phase: batch (0/1 used)
    const int uu = tid & 63;          // update phase: hidden unit
    const bool upd = (tid < GB * 64);
    const bool is_g = ((tid >> 6) == 2);   // gate rows 128..191 -> tanh
    float creg = 0.0f;

    __syncthreads();

    for (int t = 0; t < S_; ++t) {
        if constexpr (IN > 0) { if (xact) xh[xb * KD + xk] = pre0; }
        __syncthreads();              // barrier 1: x_t / h_{t-1} visible

        // prefetch next step's input
        float nxt0 = 0.0f, nxt1 = 0.0f;
        if (t + 1 < S_) {
            if constexpr (IN > 0) {
                if (xact) nxt0 = xp0[(size_t)(t + 1) * IN];
            } else {
                nxt0 = xp0[(size_t)(t + 1) * 256];
                nxt1 = xp1[(size_t)(t + 1) * 256];
            }
        }

        // gates: dot(w_row, [x|h]) for GB batches, f32x2-packed
        ull acc0 = 0ull, acc1 = 0ull;
        const UPair* v0 = reinterpret_cast<const UPair*>(xh);
        const UPair* v1 = reinterpret_cast<const UPair*>(xh + KD);
#pragma unroll
        for (int k = 0; k < N4; ++k) {
            const ull wlo = wv[2 * k];
            const ull whi = wv[2 * k + 1];
            UPair a;
            a = v0[k]; acc0 = ffma2(wlo, a.lo, acc0); acc0 = ffma2(whi, a.hi, acc0);
            a = v1[k]; acc1 = ffma2(wlo, a.lo, acc1); acc1 = ffma2(whi, a.hi, acc1);
        }
        float z0, z1;
        if constexpr (IN > 0) {
            z0 = hadd2(acc0) + myb;
            z1 = hadd2(acc1) + myb;
        } else {
            z0 = hadd2(acc0) + pre0;   // xp already includes bias
            z1 = hadd2(acc1) + pre1;
        }
        float a0, a1;
        if (is_g) { a0 = tanha(z0); a1 = tanha(z1); }
        else      { a0 = sigf(z0);  a1 = sigf(z1);  }
        gsh[tid]       = a0;
        gsh[256 + tid] = a1;
        pre0 = nxt0; pre1 = nxt1;
        __syncthreads();              // barrier 2: gates visible

        // state update: thread -> (batch ub, unit uu); c in register
        if (upd) {
            const float* gb = gsh + ub * 256;
            const float gi = gb[uu];
            const float gf = gb[64 + uu];
            const float gg = gb[128 + uu];
            const float go = gb[192 + uu];
            creg = gf * creg + gi * gg;
            const float h = go * tanha(creg);
            xh[ub * KD + IN + uu] = h;
            if constexpr (LAST_ONLY) {
                if (t == S_ - 1) out[(b0 + ub) * H_ + uu] = h;
            } else {
                out[((size_t)(b0 + ub) * S_ + t) * H_ + uu] = h;
            }
        }
        // next iteration's barrier 1 orders h/gsh writes against reads
    }
}

// out[b] = h_last[b] @ fc_w^T + fc_b
__global__ void fc_kernel(const float* __restrict__ hbuf,   // [B][64]
                          const float* __restrict__ fw,
                          const float* __restrict__ fb,
                          float* __restrict__ outp)
{
    int b = blockIdx.x * blockDim.x + threadIdx.x;
    if (b >= B_) return;
    const float* h = hbuf + (size_t)b * H_;
    float a0 = fb[0], a1 = fb[1];
#pragma unroll
    for (int k = 0; k < H_; ++k) {
        float hv = h[k];
        a0 += hv * fw[k];
        a1 += hv * fw[H_ + k];
    }
    outp[b * 2 + 0] = a0;
    outp[b * 2 + 1] = a1;
}

extern "C" void kernel_launch(void* const* d_in, const int* in_sizes, int n_in,
                              void* d_out, int out_size)
{
    const float* x    = (const float*)d_in[0];
    const float* Wih0 = (const float*)d_in[1];
    const float* Whh0 = (const float*)d_in[2];
    const float* bih0 = (const float*)d_in[3];
    const float* bhh0 = (const float*)d_in[4];
    const float* Wih1 = (const float*)d_in[5];
    const float* Whh1 = (const float*)d_in[6];
    const float* bih1 = (const float*)d_in[7];
    const float* bhh1 = (const float*)d_in[8];
    const float* Wih2 = (const float*)d_in[9];
    const float* Whh2 = (const float*)d_in[10];
    const float* bih2 = (const float*)d_in[11];
    const float* bhh2 = (const float*)d_in[12];
    const float* fc_w = (const float*)d_in[13];
    const float* fc_b = (const float*)d_in[14];
    float* out = (float*)d_out;

    float *h0 = nullptr, *h1 = nullptr, *xp = nullptr, *hlast = nullptr;
    cudaGetSymbolAddress((void**)&h0, g_h0);
    cudaGetSymbolAddress((void**)&h1, g_h1);
    cudaGetSymbolAddress((void**)&xp, g_xp);
    cudaGetSymbolAddress((void**)&hlast, g_hlast);

    const int PGRID = B_ * (S_ / PST);   // 8192

    // layer 0: x inline (input dim 4)
    recur_kernel<4, false><<<NCTA, NTH>>>(x, Wih0, Whh0, bih0, bhh0, h0);
    // layer 1: bulk input projection, then h-only recurrence
    proj_kernel<<<PGRID, NTH>>>(h0, Wih1, bih1, bhh1, xp);
    recur_kernel<0, false><<<NCTA, NTH>>>(xp, nullptr, Whh1, nullptr, nullptr, h1);
    // layer 2
    proj_kernel<<<PGRID, NTH>>>(h1, Wih2, bih2, bhh2, xp);
    recur_kernel<0, true><<<NCTA, NTH>>>(xp, nullptr, Whh2, nullptr, nullptr, hlast);
    // final linear
    fc_kernel<<<(B_ + 255) / 256, 256>>>(hlast, fc_w, fc_b, out);
}

// round 5
// speedup vs baseline: 1.7787x; 1.0053x over previous
#include <cuda_runtime.h>
#include <cstddef>

typedef unsigned long long ull;

#define B_   512
#define S_   2048
#define H_   64
#define GB   4                  // batch per recurrent CTA
#define NCTA (B_ / GB)          // 128 CTAs -> 1 per SM
#define NTH  256
#define PST  128                // proj s-tile

// Scratch (sanctioned __device__ globals)
__device__ float g_h0[(size_t)B_ * S_ * H_];
__device__ float g_h1[(size_t)B_ * S_ * H_];
__device__ float g_xp[(size_t)B_ * S_ * 4 * H_];
__device__ float g_hlast[B_ * H_];

struct alignas(16) UPair { ull lo, hi; };

__device__ __forceinline__ float ex2a(float x) {
    float y; asm("ex2.approx.ftz.f32 %0, %1;" : "=f"(y) : "f"(x)); return y;
}
__device__ __forceinline__ float rcpa(float x) {
    float y; asm("rcp.approx.ftz.f32 %0, %1;" : "=f"(y) : "f"(x)); return y;
}
__device__ __forceinline__ float sigf(float z) {
    return rcpa(1.0f + ex2a(-1.4426950408889634f * z));
}
__device__ __forceinline__ float tanha(float z) {
    return 1.0f - 2.0f * rcpa(1.0f + ex2a(2.8853900817779268f * z));
}
__device__ __forceinline__ ull ffma2(ull a, ull b, ull c) {
    ull d;
    asm("fma.rn.f32x2 %0, %1, %2, %3;" : "=l"(d) : "l"(a), "l"(b), "l"(c));
    return d;
}
__device__ __forceinline__ float hadd2(ull v) {
    float lo, hi;
    asm("mov.b64 {%0, %1}, %2;" : "=f"(lo), "=f"(hi) : "l"(v));
    return lo + hi;
}

// ---------------------------------------------------------------------------
// Bulk input projection: out[b][s][r] = dot(in[b][s][:64], W[r][:64]) + bias[r]
// ---------------------------------------------------------------------------
__global__ void __launch_bounds__(NTH, 2)
proj_kernel(const float* __restrict__ in,    // [B][S][64]
            const float* __restrict__ W,     // [256][64]
            const float* __restrict__ bih,
            const float* __restrict__ bhh,
            float* __restrict__ out)         // [B][S][256]
{
    __shared__ __align__(16) float xin[PST * H_];
    const int tid   = threadIdx.x;
    const int stile = blockIdx.x & (S_ / PST - 1);
    const int b     = blockIdx.x / (S_ / PST);
    const size_t base = (size_t)b * S_ + (size_t)stile * PST;

    ull wv[32];
    {
        const ull* wp = reinterpret_cast<const ull*>(W + tid * H_);
#pragma unroll
        for (int p = 0; p < 32; ++p) wv[p] = wp[p];
    }
    const float myb = bih[tid] + bhh[tid];

    {
        const float4* gsrc = reinterpret_cast<const float4*>(in + base * H_);
        float4* sdst = reinterpret_cast<float4*>(xin);
        for (int i = tid; i < PST * H_ / 4; i += NTH) sdst[i] = gsrc[i];
    }
    __syncthreads();

    // 8 independent s-chains per iteration for ILP
    for (int sq = 0; sq < PST; sq += 8) {
        ull ac[8];
#pragma unroll
        for (int j = 0; j < 8; ++j) ac[j] = 0ull;
#pragma unroll
        for (int k = 0; k < 16; ++k) {
            const ull wlo = wv[2 * k], whi = wv[2 * k + 1];
#pragma unroll
            for (int j = 0; j < 8; ++j) {
                const UPair a = reinterpret_cast<const UPair*>(xin + (sq + j) * H_)[k];
                ac[j] = ffma2(wlo, a.lo, ac[j]);
                ac[j] = ffma2(whi, a.hi, ac[j]);
            }
        }
#pragma unroll
        for (int j = 0; j < 8; ++j)
            out[(base + sq + j) * 256 + tid] = hadd2(ac[j]) + myb;
    }
}

// ---------------------------------------------------------------------------
// Recurrent kernel. GB=4 batches/CTA, 128 CTAs (1/SM), 256 threads.
// Thread mapping (gates): rows (ra, ra+128) x batches (bp, bp+1);
// each LDS.128 of [x|h] feeds 4 FFMA2. Weights register-resident.
// IN=4: layer 0, x inline, bias in registers.
// IN=0: z-init from precomputed xp[b][t][256] (bias folded in).
// ---------------------------------------------------------------------------
template <int IN, bool LAST_ONLY>
__global__ void __launch_bounds__(NTH, 1)
recur_kernel(const float* __restrict__ xin,   // IN=4: x[B][S][4]; IN=0: xp[B][S][256]
             const float* __restrict__ Wih,
             const float* __restrict__ Whh,
             const float* __restrict__ bih,
             const float* __restrict__ bhh,
             float* __restrict__ out)
{
    constexpr int KD = IN + H_;       // 68 or 64
    constexpr int N4 = KD / 4;

    __shared__ __align__(16) float xh[GB * KD];    // per-batch [x_t | h]
    __shared__ __align__(16) float gsh[GB * 256];  // activated gates [batch][row]

    const int tid = threadIdx.x;
    const int b0  = blockIdx.x * GB;
    const int ra  = tid & 127;        // row a (gates i/f)
    const int rb  = ra + 128;         // row b (gates g/o)
    const int bp  = (tid >> 7) * 2;   // batch pair: {0,1} or {2,3}
    const bool rb_tanh = (ra < 64);   // row b is gate g for ra<64 (warp-uniform)

    // --- weights for rows ra and rb, as b64 k-pairs ---
    ull wa[KD / 2], wb[KD / 2];
    if constexpr (IN > 0) {
        const ull* wia = reinterpret_cast<const ull*>(Wih + ra * IN);
        const ull* wib = reinterpret_cast<const ull*>(Wih + rb * IN);
#pragma unroll
        for (int p = 0; p < IN / 2; ++p) { wa[p] = wia[p]; wb[p] = wib[p]; }
    }
    {
        const ull* wha = reinterpret_cast<const ull*>(Whh + ra * H_);
        const ull* whb = reinterpret_cast<const ull*>(Whh + rb * H_);
#pragma unroll
        for (int p = 0; p < H_ / 2; ++p) {
            wa[IN / 2 + p] = wha[p];
            wb[IN / 2 + p] = whb[p];
        }
    }

    float biasA = 0.0f, biasB = 0.0f;
    if constexpr (IN > 0) {
        biasA = bih[ra] + bhh[ra];
        biasB = bih[rb] + bhh[rb];
    }

    for (int i = tid; i < GB * KD; i += NTH) xh[i] = 0.0f;

    // --- per-step input state ---
    bool xact = false; int xb = 0, xk = 0;
    const float* xptr = nullptr;
    const float* pA0 = nullptr; const float* pA1 = nullptr;
    float xpre = 0.0f;
    float pa0 = 0.0f, pb0 = 0.0f, pa1 = 0.0f, pb1 = 0.0f;
    if constexpr (IN > 0) {
        xact = (tid < GB * IN);
        xb   = xact ? (tid / IN) : 0;
        xk   = xact ? (tid - xb * IN) : 0;
        xptr = xin + ((size_t)(b0 + xb)) * S_ * IN + xk;
        xpre = xact ? xptr[0] : 0.0f;
    } else {
        pA0 = xin + ((size_t)(b0 + bp)) * S_ * 256 + ra;
        pA1 = xin + ((size_t)(b0 + bp + 1)) * S_ * 256 + ra;
        pa0 = pA0[0];   pb0 = pA0[128];
        pa1 = pA1[0];   pb1 = pA1[128];
    }

    const int ub = tid >> 6;          // update phase: batch 0..3
    const int uu = tid & 63;          // update phase: hidden unit
    float creg = 0.0f;

    __syncthreads();

    for (int t = 0; t < S_; ++t) {
        if constexpr (IN > 0) { if (xact) xh[xb * KD + xk] = xpre; }
        __syncthreads();              // barrier 1: x_t / h_{t-1} visible

        // prefetch next step's input (hidden under the FMA loop)
        float nx = 0.0f, na0 = 0.0f, nb0 = 0.0f, na1 = 0.0f, nb1 = 0.0f;
        if (t + 1 < S_) {
            if constexpr (IN > 0) {
                if (xact) nx = xptr[(size_t)(t + 1) * IN];
            } else {
                const size_t o = (size_t)(t + 1) * 256;
                na0 = pA0[o]; nb0 = pA0[o + 128];
                na1 = pA1[o]; nb1 = pA1[o + 128];
            }
        }

        // --- gates: 4 dots (2 rows x 2 batches), f32x2-packed ---
        ull A0 = 0ull, B0 = 0ull, A1 = 0ull, B1 = 0ull;
        const UPair* v0 = reinterpret_cast<const UPair*>(xh + bp * KD);
        const UPair* v1 = reinterpret_cast<const UPair*>(xh + (bp + 1) * KD);
#pragma unroll
        for (int k = 0; k < N4; ++k) {
            const ull walo = wa[2 * k], wahi = wa[2 * k + 1];
            const ull wblo = wb[2 * k], wbhi = wb[2 * k + 1];
            const UPair a0v = v0[k];
            const UPair a1v = v1[k];
            A0 = ffma2(walo, a0v.lo, A0); A0 = ffma2(wahi, a0v.hi, A0);
            B0 = ffma2(wblo, a0v.lo, B0); B0 = ffma2(wbhi, a0v.hi, B0);
            A1 = ffma2(walo, a1v.lo, A1); A1 = ffma2(wahi, a1v.hi, A1);
            B1 = ffma2(wblo, a1v.lo, B1); B1 = ffma2(wbhi, a1v.hi, B1);
        }
        float zA0, zB0, zA1, zB1;
        if constexpr (IN > 0) {
            zA0 = hadd2(A0) + biasA;  zB0 = hadd2(B0) + biasB;
            zA1 = hadd2(A1) + biasA;  zB1 = hadd2(B1) + biasB;
        } else {
            zA0 = hadd2(A0) + pa0;    zB0 = hadd2(B0) + pb0;
            zA1 = hadd2(A1) + pa1;    zB1 = hadd2(B1) + pb1;
        }
        // row a is gate i or f -> sigmoid; row b is g (tanh) or o (sigmoid)
        const float ga0 = sigf(zA0);
        const float ga1 = sigf(zA1);
        const float gb0 = rb_tanh ? tanha(zB0) : sigf(zB0);
        const float gb1 = rb_tanh ? tanha(zB1) : sigf(zB1);
        gsh[bp * 256 + ra]       = ga0;
        gsh[bp * 256 + rb]       = gb0;
        gsh[(bp + 1) * 256 + ra] = ga1;
        gsh[(bp + 1) * 256 + rb] = gb1;
        if constexpr (IN > 0) { xpre = nx; }
        else { pa0 = na0; pb0 = nb0; pa1 = na1; pb1 = nb1; }
        __syncthreads();              // barrier 2: gates visible

        // --- state update: thread -> (batch ub, unit uu); c in register ---
        {
            const float* gp = gsh + ub * 256 + uu;
            const float gi = gp[0];
            const float gf = gp[64];
            const float gg = gp[128];
            const float go = gp[192];
            creg = gf * creg + gi * gg;
            const float h = go * tanha(creg);
            xh[ub * KD + IN + uu] = h;
            if constexpr (LAST_ONLY) {
                if (t == S_ - 1) out[(b0 + ub) * H_ + uu] = h;
            } else {
                out[((size_t)(b0 + ub) * S_ + t) * H_ + uu] = h;
            }
        }
        // next iteration's barrier 1 orders h/gsh writes against reads
    }
}

// out[b] = h_last[b] @ fc_w^T + fc_b
__global__ void fc_kernel(const float* __restrict__ hbuf,
                          const float* __restrict__ fw,
                          const float* __restrict__ fb,
                          float* __restrict__ outp)
{
    int b = blockIdx.x * blockDim.x + threadIdx.x;
    if (b >= B_) return;
    const float* h = hbuf + (size_t)b * H_;
    float a0 = fb[0], a1 = fb[1];
#pragma unroll
    for (int k = 0; k < H_; ++k) {
        float hv = h[k];
        a0 += hv * fw[k];
        a1 += hv * fw[H_ + k];
    }
    outp[b * 2 + 0] = a0;
    outp[b * 2 + 1] = a1;
}

extern "C" void kernel_launch(void* const* d_in, const int* in_sizes, int n_in,
                              void* d_out, int out_size)
{
    const float* x    = (const float*)d_in[0];
    const float* Wih0 = (const float*)d_in[1];
    const float* Whh0 = (const float*)d_in[2];
    const float* bih0 = (const float*)d_in[3];
    const float* bhh0 = (const float*)d_in[4];
    const float* Wih1 = (const float*)d_in[5];
    const float* Whh1 = (const float*)d_in[6];
    const float* bih1 = (const float*)d_in[7];
    const float* bhh1 = (const float*)d_in[8];
    const float* Wih2 = (const float*)d_in[9];
    const float* Whh2 = (const float*)d_in[10];
    const float* bih2 = (const float*)d_in[11];
    const float* bhh2 = (const float*)d_in[12];
    const float* fc_w = (const float*)d_in[13];
    const float* fc_b = (const float*)d_in[14];
    float* out = (float*)d_out;

    float *h0 = nullptr, *h1 = nullptr, *xp = nullptr, *hlast = nullptr;
    cudaGetSymbolAddress((void**)&h0, g_h0);
    cudaGetSymbolAddress((void**)&h1, g_h1);
    cudaGetSymbolAddress((void**)&xp, g_xp);
    cudaGetSymbolAddress((void**)&hlast, g_hlast);

    const int PGRID = B_ * (S_ / PST);   // 8192

    recur_kernel<4, false><<<NCTA, NTH>>>(x, Wih0, Whh0, bih0, bhh0, h0);
    proj_kernel<<<PGRID, NTH>>>(h0, Wih1, bih1, bhh1, xp);
    recur_kernel<0, false><<<NCTA, NTH>>>(xp, nullptr, Whh1, nullptr, nullptr, h1);
    proj_kernel<<<PGRID, NTH>>>(h1, Wih2, bih2, bhh2, xp);
    recur_kernel<0, true><<<NCTA, NTH>>>(xp, nullptr, Whh2, nullptr, nullptr, hlast);
    fc_kernel<<<(B_ + 255) / 256, 256>>>(hlast, fc_w, fc_b, out);
}